// round 13
// baseline (speedup 1.0000x reference)
#include <cuda_runtime.h>
#include <cstdint>

// Problem constants (B=64, D=256, H=32, W=32, K=1024)
#define TOK_N   65536
#define DDIM    256
#define KCODES  1024

// Tiling: 32 tx (codes) x 16 ty (tokens); TM=8 tokens, TN=8 codes per thread.
// 512 threads = 16 warps = 4 warps/SMSP (double R11's latency coverage).
// Code assignment INTERLEAVED: thread tx owns codes {q*128 + tx*4 + j},
// q=0..1, j=0..3 -> every B LDS.128 is 32 lanes x 16B linear = conflict-free.
// A fragment address is warp-uniform (ty const per warp) -> LDS broadcast.
#define BM      128
#define BN      256
#define BD      32
#define TM      8
#define TN      8
#define NTHREADS 512
#define NCHUNK  32            // (KCODES/BN) tiles * (DDIM/BD) d-chunks

#define XS_FLOATS (DDIM*BM)          // 32768 (128 KB)
#define CS_FLOATS (BD*BN)            // 8192  (32 KB per buffer)
#define SMEM_BYTES ((XS_FLOATS + 2*CS_FLOATS) * 4)   // 192 KB

// Scratch in device globals (no allocations allowed in kernel_launch)
__device__ float g_cbT[DDIM * KCODES];      // transposed codebook [d][k]
__device__ float g_cnorm_half[KCODES];      // 0.5 * ||c_k||^2

// ---------------------------------------------------------------------------
__device__ __forceinline__ float2 ffma2(float2 a, float2 b, float2 c) {
    unsigned long long ua = *reinterpret_cast<unsigned long long*>(&a);
    unsigned long long ub = *reinterpret_cast<unsigned long long*>(&b);
    unsigned long long uc = *reinterpret_cast<unsigned long long*>(&c);
    unsigned long long ud;
    asm("fma.rn.f32x2 %0, %1, %2, %3;" : "=l"(ud) : "l"(ua), "l"(ub), "l"(uc));
    float2 d;
    *reinterpret_cast<unsigned long long*>(&d) = ud;
    return d;
}

__device__ __forceinline__ void cp_async16(uint32_t saddr, const float* gptr) {
    asm volatile("cp.async.cg.shared.global [%0], [%1], 16;"
                 :: "r"(saddr), "l"(gptr));
}
#define CP_COMMIT() asm volatile("cp.async.commit_group;" ::: "memory")
#define CP_WAIT_ALL() asm volatile("cp.async.wait_group 0;" ::: "memory")

// ---------------------------------------------------------------------------
// Prep: transpose codebook to [D][K] and compute 0.5*||c||^2 per code.
// ---------------------------------------------------------------------------
__global__ void __launch_bounds__(256) vq_prep(const float* __restrict__ cb) {
    int k = blockIdx.x;
    int d = threadIdx.x;
    float v = cb[k * DDIM + d];
    g_cbT[d * KCODES + k] = v;

    __shared__ float red[256];
    red[d] = v * v;
    __syncthreads();
    #pragma unroll
    for (int s = 128; s > 0; s >>= 1) {
        if (d < s) red[d] += red[d + s];
        __syncthreads();
    }
    if (d == 0) g_cnorm_half[k] = 0.5f * red[0];
}

// ---------------------------------------------------------------------------
// Main: per block, 128 tokens vs all 1024 codes.
//   NUMERICS CONTRACT (bit-identical to the R6/R11 passing runs): acc starts
//   at 0, fp32 fma over d = 0..255 sequentially with a single accumulator per
//   (token, code), subtract 0.5||c||^2 in the epilogue. Do NOT reorder.
// ---------------------------------------------------------------------------
__global__ void __launch_bounds__(NTHREADS, 1)
vq_main(const float* __restrict__ x,
        const float* __restrict__ cb,
        float* __restrict__ out,
        int halfElems) {
    extern __shared__ float smem[];
    float* xs = smem;                     // [DDIM][BM]
    float* cs = smem + XS_FLOATS;         // 2 x [BD][BN] (buf0 reused for reduce)

    const int tid = threadIdx.x;
    const int tx = tid & 31;              // code lane (8 codes each)
    const int ty = tid >> 5;              // token group (8 tokens each)

    const uint32_t xs_u = (uint32_t)__cvta_generic_to_shared(xs);
    const uint32_t cs_u = (uint32_t)__cvta_generic_to_shared(cs);

    const int m0  = blockIdx.x * BM;      // first flat token (NHWC order)
    const int b   = m0 >> 10;
    const int hw0 = m0 & 1023;            // multiple of 128
    const float* xbase = x + (long long)b * (DDIM * 1024) + hw0;

    // ---- issue x-slab loads (no data registers: cp.async) ----
    #pragma unroll 4
    for (int f = tid; f < XS_FLOATS / 4; f += NTHREADS) {
        int d  = f >> 5;                  // BM/4 = 32 float4 per d-row
        int m4 = f & 31;
        cp_async16(xs_u + (uint32_t)(d * BM + m4 * 4) * 4,
                   xbase + d * 1024 + m4 * 4);
    }
    CP_COMMIT();

    // ---- issue chunk 0 (tile 0, d0=0) into buffer 0 ----
    #pragma unroll
    for (int f = tid; f < CS_FLOATS / 4; f += NTHREADS) {
        int dd = f >> 6;                  // BN/4 = 64 float4 per row
        int n4 = f & 63;
        cp_async16(cs_u + (uint32_t)(dd * BN + n4 * 4) * 4,
                   &g_cbT[dd * KCODES + n4 * 4]);
    }
    CP_COMMIT();

    float bestv[TM];
    int   besti[TM];
    #pragma unroll
    for (int i = 0; i < TM; i++) { bestv[i] = -1e30f; besti[i] = 0; }

    float2 acc[TM][TN / 2];               // 64 scalar accumulators

    for (int c = 0; c < NCHUNK; ++c) {
        CP_WAIT_ALL();        // chunk c (and xs when c==0) landed
        __syncthreads();      // all threads; also: reads of the other buffer
                              // (compute of c-1) are complete.

        // Prefetch chunk c+1 into the other buffer (overlaps compute below)
        if (c + 1 < NCHUNK) {
            const int tn = c + 1;
            const int n0n = (tn >> 3) * BN;
            const int d0n = (tn & 7) * BD;
            const uint32_t dst = cs_u + (uint32_t)((tn & 1) * CS_FLOATS) * 4;
            #pragma unroll
            for (int f = tid; f < CS_FLOATS / 4; f += NTHREADS) {
                int dd = f >> 6;
                int n4 = f & 63;
                cp_async16(dst + (uint32_t)(dd * BN + n4 * 4) * 4,
                           &g_cbT[(d0n + dd) * KCODES + n0n + n4 * 4]);
            }
            CP_COMMIT();
        }

        const float* cb_s = cs + (c & 1) * CS_FLOATS;
        const int d0 = (c & 7) * BD;

        if ((c & 7) == 0) {
            #pragma unroll
            for (int i = 0; i < TM; i++)
                #pragma unroll
                for (int jp = 0; jp < TN / 2; jp++)
                    acc[i][jp] = make_float2(0.f, 0.f);
        }

        #pragma unroll 4
        for (int dd = 0; dd < BD; ++dd) {
            // A fragment: 8 tokens; address warp-uniform -> smem broadcast
            float4 av0 = *reinterpret_cast<const float4*>(
                &xs[(d0 + dd) * BM + ty * TM]);
            float4 av1 = *reinterpret_cast<const float4*>(
                &xs[(d0 + dd) * BM + ty * TM + 4]);
            float a_[TM] = { av0.x, av0.y, av0.z, av0.w,
                             av1.x, av1.y, av1.z, av1.w };
            // B fragment: codes q*128 + tx*4 (+0..3); 32 lanes x 16B linear
            float2 bp[TN / 2];
            #pragma unroll
            for (int q = 0; q < 2; q++) {
                float4 bv = *reinterpret_cast<const float4*>(
                    &cb_s[dd * BN + q * 128 + tx * 4]);
                bp[q * 2]     = make_float2(bv.x, bv.y);
                bp[q * 2 + 1] = make_float2(bv.z, bv.w);
            }
            #pragma unroll
            for (int i = 0; i < TM; i++) {
                float2 pa = make_float2(a_[i], a_[i]);
                #pragma unroll
                for (int jp = 0; jp < TN / 2; jp++)
                    acc[i][jp] = ffma2(pa, bp[jp], acc[i][jp]);
            }
        }

        // Tile epilogue: subtract 0.5||c||^2 HERE (exact contract arithmetic),
        // running argmax. Within-thread visit order ascending n (q, then j),
        // strict '>' keeps lowest index on exact ties.
        if ((c & 7) == 7) {
            const int n0 = (c >> 3) * BN;
            #pragma unroll
            for (int q = 0; q < 2; q++) {
                const int n = n0 + q * 128 + tx * 4;
                float4 cn = *reinterpret_cast<const float4*>(&g_cnorm_half[n]);
                const float cn_[4] = { cn.x, cn.y, cn.z, cn.w };
                #pragma unroll
                for (int j2 = 0; j2 < 2; j2++) {
                    #pragma unroll
                    for (int i = 0; i < TM; i++) {
                        float s0 = acc[i][q * 2 + j2].x - cn_[j2 * 2];
                        float s1 = acc[i][q * 2 + j2].y - cn_[j2 * 2 + 1];
                        if (s0 > bestv[i]) { bestv[i] = s0; besti[i] = n + j2 * 2; }
                        if (s1 > bestv[i]) { bestv[i] = s1; besti[i] = n + j2 * 2 + 1; }
                    }
                }
            }
        }
    }

    // Cross-thread argmax reduce over the 32 tx lanes (tie-break -> lowest idx)
    __syncthreads();
    float* rv = cs;                                   // [BM][32]
    int*   ri = reinterpret_cast<int*>(cs + BM * 32); // [BM][32]
    #pragma unroll
    for (int i = 0; i < TM; i++) {
        int m = ty * TM + i;
        rv[m * 32 + tx] = bestv[i];
        ri[m * 32 + tx] = besti[i];
    }
    __syncthreads();
    int* fidx = reinterpret_cast<int*>(cs + 2 * BM * 32);
    if (tid < BM) {
        float bv = rv[tid * 32];
        int   bi = ri[tid * 32];
        #pragma unroll
        for (int s = 1; s < 32; s++) {
            float v  = rv[tid * 32 + s];
            int   ix = ri[tid * 32 + s];
            if (v > bv || (v == bv && ix < bi)) { bv = v; bi = ix; }
        }
        fidx[tid] = bi;
    }
    __syncthreads();

    // Gather + write both outputs. Raw reshape => out linear index = n*D + d.
    const float4* cb4 = reinterpret_cast<const float4*>(cb);
    float4* o1 = reinterpret_cast<float4*>(out);
    float4* o2 = reinterpret_cast<float4*>(out + halfElems);
    #pragma unroll 4
    for (int f = tid; f < BM * (DDIM / 4); f += NTHREADS) {
        int m  = f >> 6;              // DDIM/4 = 64 float4 per token
        int d4 = f & 63;
        float4 v = cb4[fidx[m] * (DDIM / 4) + d4];
        long long o = (long long)(m0 + m) * (DDIM / 4) + d4;
        o1[o] = v;
        o2[o] = v;
    }
}

// ---------------------------------------------------------------------------
extern "C" void kernel_launch(void* const* d_in, const int* in_sizes, int n_in,
                              void* d_out, int out_size) {
    const float* x  = reinterpret_cast<const float*>(d_in[0]);
    const float* cb = reinterpret_cast<const float*>(d_in[1]);
    if (n_in >= 2 && in_sizes[0] == KCODES * DDIM && in_sizes[1] != KCODES * DDIM) {
        const float* tmp = x; x = cb; cb = tmp;
    }
    float* out = reinterpret_cast<float*>(d_out);
    int halfElems = out_size / 2;     // (z_hat, z_q) concatenated; identical forward

    cudaFuncSetAttribute(vq_main, cudaFuncAttributeMaxDynamicSharedMemorySize, SMEM_BYTES);

    vq_prep<<<KCODES, 256>>>(cb);
    vq_main<<<TOK_N / BM, NTHREADS, SMEM_BYTES>>>(x, cb, out, halfElems);
}

// round 14
// speedup vs baseline: 1.0017x; 1.0017x over previous
#include <cuda_runtime.h>
#include <cstdint>

// Problem constants (B=64, D=256, H=32, W=32, K=1024)
#define TOK_N   65536
#define DDIM    256
#define KCODES  1024

// Tiling: 32 tx (codes) x 16 ty (tokens); TM=8 tokens, TN=8 codes per thread.
// 512 threads = 16 warps = 4 warps/SMSP (double R11's latency coverage).
// Code assignment INTERLEAVED: thread tx owns codes {q*128 + tx*4 + j},
// q=0..1, j=0..3 -> every B LDS.128 is 32 lanes x 16B linear = conflict-free.
// A fragment address is warp-uniform (ty const per warp) -> LDS broadcast.
#define BM      128
#define BN      256
#define BD      32
#define TM      8
#define TN      8
#define NTHREADS 512
#define NCHUNK  32            // (KCODES/BN) tiles * (DDIM/BD) d-chunks

#define XS_FLOATS (DDIM*BM)          // 32768 (128 KB)
#define CS_FLOATS (BD*BN)            // 8192  (32 KB per buffer)
#define SMEM_BYTES ((XS_FLOATS + 2*CS_FLOATS) * 4)   // 192 KB

// Scratch in device globals (no allocations allowed in kernel_launch)
__device__ float g_cbT[DDIM * KCODES];      // transposed codebook [d][k]
__device__ float g_cnorm_half[KCODES];      // 0.5 * ||c_k||^2

// ---------------------------------------------------------------------------
__device__ __forceinline__ float2 ffma2(float2 a, float2 b, float2 c) {
    unsigned long long ua = *reinterpret_cast<unsigned long long*>(&a);
    unsigned long long ub = *reinterpret_cast<unsigned long long*>(&b);
    unsigned long long uc = *reinterpret_cast<unsigned long long*>(&c);
    unsigned long long ud;
    asm("fma.rn.f32x2 %0, %1, %2, %3;" : "=l"(ud) : "l"(ua), "l"(ub), "l"(uc));
    float2 d;
    *reinterpret_cast<unsigned long long*>(&d) = ud;
    return d;
}

__device__ __forceinline__ void cp_async16(uint32_t saddr, const float* gptr) {
    asm volatile("cp.async.cg.shared.global [%0], [%1], 16;"
                 :: "r"(saddr), "l"(gptr));
}
#define CP_COMMIT() asm volatile("cp.async.commit_group;" ::: "memory")
#define CP_WAIT_ALL() asm volatile("cp.async.wait_group 0;" ::: "memory")

// ---------------------------------------------------------------------------
// Prep: transpose codebook to [D][K] and compute 0.5*||c||^2 per code.
// ---------------------------------------------------------------------------
__global__ void __launch_bounds__(256) vq_prep(const float* __restrict__ cb) {
    int k = blockIdx.x;
    int d = threadIdx.x;
    float v = cb[k * DDIM + d];
    g_cbT[d * KCODES + k] = v;

    __shared__ float red[256];
    red[d] = v * v;
    __syncthreads();
    #pragma unroll
    for (int s = 128; s > 0; s >>= 1) {
        if (d < s) red[d] += red[d + s];
        __syncthreads();
    }
    if (d == 0) g_cnorm_half[k] = 0.5f * red[0];
}

// ---------------------------------------------------------------------------
// Main: per block, 128 tokens vs all 1024 codes.
//   NUMERICS CONTRACT (bit-identical to the R6/R11 passing runs): acc starts
//   at 0, fp32 fma over d = 0..255 sequentially with a single accumulator per
//   (token, code), subtract 0.5||c||^2 in the epilogue. Do NOT reorder.
// ---------------------------------------------------------------------------
__global__ void __launch_bounds__(NTHREADS, 1)
vq_main(const float* __restrict__ x,
        const float* __restrict__ cb,
        float* __restrict__ out,
        int halfElems) {
    extern __shared__ float smem[];
    float* xs = smem;                     // [DDIM][BM]
    float* cs = smem + XS_FLOATS;         // 2 x [BD][BN] (buf0 reused for reduce)

    const int tid = threadIdx.x;
    const int tx = tid & 31;              // code lane (8 codes each)
    const int ty = tid >> 5;              // token group (8 tokens each)

    const uint32_t xs_u = (uint32_t)__cvta_generic_to_shared(xs);
    const uint32_t cs_u = (uint32_t)__cvta_generic_to_shared(cs);

    const int m0  = blockIdx.x * BM;      // first flat token (NHWC order)
    const int b   = m0 >> 10;
    const int hw0 = m0 & 1023;            // multiple of 128
    const float* xbase = x + (long long)b * (DDIM * 1024) + hw0;

    // ---- issue x-slab loads (no data registers: cp.async) ----
    #pragma unroll 4
    for (int f = tid; f < XS_FLOATS / 4; f += NTHREADS) {
        int d  = f >> 5;                  // BM/4 = 32 float4 per d-row
        int m4 = f & 31;
        cp_async16(xs_u + (uint32_t)(d * BM + m4 * 4) * 4,
                   xbase + d * 1024 + m4 * 4);
    }
    CP_COMMIT();

    // ---- issue chunk 0 (tile 0, d0=0) into buffer 0 ----
    #pragma unroll
    for (int f = tid; f < CS_FLOATS / 4; f += NTHREADS) {
        int dd = f >> 6;                  // BN/4 = 64 float4 per row
        int n4 = f & 63;
        cp_async16(cs_u + (uint32_t)(dd * BN + n4 * 4) * 4,
                   &g_cbT[dd * KCODES + n4 * 4]);
    }
    CP_COMMIT();

    float bestv[TM];
    int   besti[TM];
    #pragma unroll
    for (int i = 0; i < TM; i++) { bestv[i] = -1e30f; besti[i] = 0; }

    float2 acc[TM][TN / 2];               // 64 scalar accumulators

    for (int c = 0; c < NCHUNK; ++c) {
        CP_WAIT_ALL();        // chunk c (and xs when c==0) landed
        __syncthreads();      // all threads; also: reads of the other buffer
                              // (compute of c-1) are complete.

        // Prefetch chunk c+1 into the other buffer (overlaps compute below)
        if (c + 1 < NCHUNK) {
            const int tn = c + 1;
            const int n0n = (tn >> 3) * BN;
            const int d0n = (tn & 7) * BD;
            const uint32_t dst = cs_u + (uint32_t)((tn & 1) * CS_FLOATS) * 4;
            #pragma unroll
            for (int f = tid; f < CS_FLOATS / 4; f += NTHREADS) {
                int dd = f >> 6;
                int n4 = f & 63;
                cp_async16(dst + (uint32_t)(dd * BN + n4 * 4) * 4,
                           &g_cbT[(d0n + dd) * KCODES + n0n + n4 * 4]);
            }
            CP_COMMIT();
        }

        const float* cb_s = cs + (c & 1) * CS_FLOATS;
        const int d0 = (c & 7) * BD;

        if ((c & 7) == 0) {
            #pragma unroll
            for (int i = 0; i < TM; i++)
                #pragma unroll
                for (int jp = 0; jp < TN / 2; jp++)
                    acc[i][jp] = make_float2(0.f, 0.f);
        }

        #pragma unroll 4
        for (int dd = 0; dd < BD; ++dd) {
            // A fragment: 8 tokens; address warp-uniform -> smem broadcast
            float4 av0 = *reinterpret_cast<const float4*>(
                &xs[(d0 + dd) * BM + ty * TM]);
            float4 av1 = *reinterpret_cast<const float4*>(
                &xs[(d0 + dd) * BM + ty * TM + 4]);
            float a_[TM] = { av0.x, av0.y, av0.z, av0.w,
                             av1.x, av1.y, av1.z, av1.w };
            // B fragment: codes q*128 + tx*4 (+0..3); 32 lanes x 16B linear
            float2 bp[TN / 2];
            #pragma unroll
            for (int q = 0; q < 2; q++) {
                float4 bv = *reinterpret_cast<const float4*>(
                    &cb_s[dd * BN + q * 128 + tx * 4]);
                bp[q * 2]     = make_float2(bv.x, bv.y);
                bp[q * 2 + 1] = make_float2(bv.z, bv.w);
            }
            #pragma unroll
            for (int i = 0; i < TM; i++) {
                float2 pa = make_float2(a_[i], a_[i]);
                #pragma unroll
                for (int jp = 0; jp < TN / 2; jp++)
                    acc[i][jp] = ffma2(pa, bp[jp], acc[i][jp]);
            }
        }

        // Tile epilogue: subtract 0.5||c||^2 HERE (exact contract arithmetic),
        // running argmax. Within-thread visit order ascending n (q, then j),
        // strict '>' keeps lowest index on exact ties.
        if ((c & 7) == 7) {
            const int n0 = (c >> 3) * BN;
            #pragma unroll
            for (int q = 0; q < 2; q++) {
                const int n = n0 + q * 128 + tx * 4;
                float4 cn = *reinterpret_cast<const float4*>(&g_cnorm_half[n]);
                const float cn_[4] = { cn.x, cn.y, cn.z, cn.w };
                #pragma unroll
                for (int j2 = 0; j2 < 2; j2++) {
                    #pragma unroll
                    for (int i = 0; i < TM; i++) {
                        float s0 = acc[i][q * 2 + j2].x - cn_[j2 * 2];
                        float s1 = acc[i][q * 2 + j2].y - cn_[j2 * 2 + 1];
                        if (s0 > bestv[i]) { bestv[i] = s0; besti[i] = n + j2 * 2; }
                        if (s1 > bestv[i]) { bestv[i] = s1; besti[i] = n + j2 * 2 + 1; }
                    }
                }
            }
        }
    }

    // Cross-thread argmax reduce over the 32 tx lanes (tie-break -> lowest idx)
    __syncthreads();
    float* rv = cs;                                   // [BM][32]
    int*   ri = reinterpret_cast<int*>(cs + BM * 32); // [BM][32]
    #pragma unroll
    for (int i = 0; i < TM; i++) {
        int m = ty * TM + i;
        rv[m * 32 + tx] = bestv[i];
        ri[m * 32 + tx] = besti[i];
    }
    __syncthreads();
    int* fidx = reinterpret_cast<int*>(cs + 2 * BM * 32);
    if (tid < BM) {
        float bv = rv[tid * 32];
        int   bi = ri[tid * 32];
        #pragma unroll
        for (int s = 1; s < 32; s++) {
            float v  = rv[tid * 32 + s];
            int   ix = ri[tid * 32 + s];
            if (v > bv || (v == bv && ix < bi)) { bv = v; bi = ix; }
        }
        fidx[tid] = bi;
    }
    __syncthreads();

    // Gather + write both outputs. Raw reshape => out linear index = n*D + d.
    const float4* cb4 = reinterpret_cast<const float4*>(cb);
    float4* o1 = reinterpret_cast<float4*>(out);
    float4* o2 = reinterpret_cast<float4*>(out + halfElems);
    #pragma unroll 4
    for (int f = tid; f < BM * (DDIM / 4); f += NTHREADS) {
        int m  = f >> 6;              // DDIM/4 = 64 float4 per token
        int d4 = f & 63;
        float4 v = cb4[fidx[m] * (DDIM / 4) + d4];
        long long o = (long long)(m0 + m) * (DDIM / 4) + d4;
        o1[o] = v;
        o2[o] = v;
    }
}

// ---------------------------------------------------------------------------
extern "C" void kernel_launch(void* const* d_in, const int* in_sizes, int n_in,
                              void* d_out, int out_size) {
    const float* x  = reinterpret_cast<const float*>(d_in[0]);
    const float* cb = reinterpret_cast<const float*>(d_in[1]);
    if (n_in >= 2 && in_sizes[0] == KCODES * DDIM && in_sizes[1] != KCODES * DDIM) {
        const float* tmp = x; x = cb; cb = tmp;
    }
    float* out = reinterpret_cast<float*>(d_out);
    int halfElems = out_size / 2;     // (z_hat, z_q) concatenated; identical forward

    cudaFuncSetAttribute(vq_main, cudaFuncAttributeMaxDynamicSharedMemorySize, SMEM_BYTES);

    vq_prep<<<KCODES, 256>>>(cb);
    vq_main<<<TOK_N / BM, NTHREADS, SMEM_BYTES>>>(x, cb, out, halfElems);
}

// round 15
// speedup vs baseline: 1.0774x; 1.0756x over previous
#include <cuda_runtime.h>
#include <cstdint>

// Problem constants (B=64, D=256, H=32, W=32, K=1024)
#define TOK_N   65536
#define DDIM    256
#define KCODES  1024

// vq_partial tiling: 32 tx (codes) x 16 ty (tokens); TM=8, TN=8 per thread.
// Each CTA: 128 tokens x 512 codes (half the codebook) -> grid = 1024 CTAs
// (6.92/7 waves on 148 SMs = 98.8% balance vs 3.46/4 = 86.5% before).
// Codebook chunks are bulk-copied (1 instr) from a chunk-contiguous layout.
#define BM      128
#define BN      256
#define BD      32
#define TM      8
#define TN      8
#define NTHREADS 512
#define NCHUNK  16            // per CTA: 2 tiles * 8 d-chunks
#define CHUNK_FLOATS (BD*BN)  // 8192 floats = 32 KB
#define CHUNK_BYTES  (CHUNK_FLOATS*4)

#define XS_FLOATS (DDIM*BM)                          // 32768 (128 KB)
#define SMEM_BYTES ((XS_FLOATS + 2*CHUNK_FLOATS) * 4) // 192 KB dynamic

// Device-global scratch (no allocations allowed in kernel_launch)
__device__ float g_cbC[DDIM * KCODES];   // chunk-contiguous codebook:
                                         // [(k>>8)*8 + (d>>5)][d&31][k&255]
__device__ float g_cnorm_half[KCODES];   // 0.5 * ||c_k||^2
__device__ float g_pv[2 * TOK_N];        // per-half best value
__device__ int   g_pi[2 * TOK_N];        // per-half best index

// ---------------------------------------------------------------------------
__device__ __forceinline__ float2 ffma2(float2 a, float2 b, float2 c) {
    unsigned long long ua = *reinterpret_cast<unsigned long long*>(&a);
    unsigned long long ub = *reinterpret_cast<unsigned long long*>(&b);
    unsigned long long uc = *reinterpret_cast<unsigned long long*>(&c);
    unsigned long long ud;
    asm("fma.rn.f32x2 %0, %1, %2, %3;" : "=l"(ud) : "l"(ua), "l"(ub), "l"(uc));
    float2 d;
    *reinterpret_cast<unsigned long long*>(&d) = ud;
    return d;
}

__device__ __forceinline__ void cp_async16(uint32_t saddr, const float* gptr) {
    asm volatile("cp.async.cg.shared.global [%0], [%1], 16;"
                 :: "r"(saddr), "l"(gptr));
}
#define CP_COMMIT()   asm volatile("cp.async.commit_group;" ::: "memory")
#define CP_WAIT_ALL() asm volatile("cp.async.wait_group 0;" ::: "memory")

// One-instruction 32KB chunk copy, completion signalled on an mbarrier.
__device__ __forceinline__ void cp_bulk(uint32_t dst_smem, const float* src,
                                        uint32_t bytes, uint32_t mbar) {
    asm volatile(
        "cp.async.bulk.shared::cluster.global.mbarrier::complete_tx::bytes "
        "[%0], [%1], %2, [%3];"
        :: "r"(dst_smem), "l"(src), "r"(bytes), "r"(mbar) : "memory");
}

#define MBAR_INIT(addr, cnt) \
    asm volatile("mbarrier.init.shared.b64 [%0], %1;" :: "r"(addr), "r"(cnt) : "memory")
#define MBAR_EXPECT_TX(addr, bytes) \
    asm volatile("mbarrier.arrive.expect_tx.shared.b64 _, [%0], %1;" \
                 :: "r"(addr), "r"(bytes) : "memory")

__device__ __forceinline__ void mbar_wait(uint32_t addr, uint32_t parity) {
    asm volatile(
        "{\n\t.reg .pred P;\n\t"
        "WL_%=:\n\t"
        "mbarrier.try_wait.parity.acquire.cta.shared::cta.b64 P, [%0], %1, 0x989680;\n\t"
        "@P bra.uni WD_%=;\n\t"
        "bra.uni WL_%=;\n\t"
        "WD_%=:\n\t}"
        :: "r"(addr), "r"(parity) : "memory");
}

// ---------------------------------------------------------------------------
// Prep: chunk-contiguous codebook + 0.5*||c||^2 per code.
// ---------------------------------------------------------------------------
__global__ void __launch_bounds__(256) vq_prep(const float* __restrict__ cb) {
    int k = blockIdx.x;
    int d = threadIdx.x;
    float v = cb[k * DDIM + d];
    g_cbC[(((k >> 8) * 8 + (d >> 5)) * CHUNK_FLOATS) + (d & 31) * BN + (k & 255)] = v;

    __shared__ float red[256];
    red[d] = v * v;
    __syncthreads();
    #pragma unroll
    for (int s = 128; s > 0; s >>= 1) {
        if (d < s) red[d] += red[d + s];
        __syncthreads();
    }
    if (d == 0) g_cnorm_half[k] = 0.5f * red[0];
}

// ---------------------------------------------------------------------------
// Partial: 128 tokens x 512 codes per CTA (half h = bid & 1).
//   NUMERICS CONTRACT (bit-identical per (token, code) to the R6/R11/R14
//   passing runs): acc starts at 0, fp32 fma over d = 0..255 sequentially with
//   a single accumulator per (token, code), subtract 0.5||c||^2 in the
//   epilogue. Do NOT reorder.
// ---------------------------------------------------------------------------
__global__ void __launch_bounds__(NTHREADS, 1)
vq_partial(const float* __restrict__ x) {
    extern __shared__ float smem[];
    float* xs = smem;                     // [DDIM][BM]
    float* cs = smem + XS_FLOATS;         // 2 x [BD][BN] (reused for reduce)
    __shared__ unsigned long long s_mbar[2];

    const int tid = threadIdx.x;
    const int tx = tid & 31;              // code lane (8 codes each)
    const int ty = tid >> 5;              // token group (8 tokens each)

    const int mb = blockIdx.x >> 1;       // token block
    const int h  = blockIdx.x & 1;        // codebook half (codes h*512..)

    const uint32_t xs_u = (uint32_t)__cvta_generic_to_shared(xs);
    const uint32_t cs_u = (uint32_t)__cvta_generic_to_shared(cs);
    const uint32_t mb_u = (uint32_t)__cvta_generic_to_shared(s_mbar);

    const int m0  = mb * BM;              // first flat token (NHWC order)
    const int b   = m0 >> 10;
    const int hw0 = m0 & 1023;            // multiple of 128
    const float* xbase = x + (long long)b * (DDIM * 1024) + hw0;

    // ---- issue x-slab loads (one time; no data registers) ----
    #pragma unroll 4
    for (int f = tid; f < XS_FLOATS / 4; f += NTHREADS) {
        int d  = f >> 5;                  // BM/4 = 32 float4 per d-row
        int m4 = f & 31;
        cp_async16(xs_u + (uint32_t)(d * BM + m4 * 4) * 4,
                   xbase + d * 1024 + m4 * 4);
    }
    CP_COMMIT();

    // ---- mbarriers + first two chunk bulk-copies ----
    if (tid == 0) {
        MBAR_INIT(mb_u, 1);
        MBAR_INIT(mb_u + 8, 1);
    }
    __syncthreads();
    if (tid == 0) {
        const float* src = g_cbC + (16 * h) * CHUNK_FLOATS;
        MBAR_EXPECT_TX(mb_u, CHUNK_BYTES);
        cp_bulk(cs_u, src, CHUNK_BYTES, mb_u);
        MBAR_EXPECT_TX(mb_u + 8, CHUNK_BYTES);
        cp_bulk(cs_u + CHUNK_BYTES, src + CHUNK_FLOATS, CHUNK_BYTES, mb_u + 8);
    }

    CP_WAIT_ALL();                        // x-slab (this thread's parts)
    __syncthreads();                      // ...all threads' parts visible

    float bestv[TM];
    int   besti[TM];
    #pragma unroll
    for (int i = 0; i < TM; i++) { bestv[i] = -1e30f; besti[i] = 0; }

    float2 acc[TM][TN / 2];               // 64 scalar accumulators

    for (int c = 0; c < NCHUNK; ++c) {
        const uint32_t mbar = mb_u + (c & 1) * 8;
        mbar_wait(mbar, (c >> 1) & 1);    // chunk c landed (acquire)

        const float* cb_s = cs + (c & 1) * CHUNK_FLOATS;
        const int d0 = (c & 7) * BD;

        if ((c & 7) == 0) {
            #pragma unroll
            for (int i = 0; i < TM; i++)
                #pragma unroll
                for (int jp = 0; jp < TN / 2; jp++)
                    acc[i][jp] = make_float2(0.f, 0.f);
        }

        #pragma unroll 4
        for (int dd = 0; dd < BD; ++dd) {
            // A fragment: 8 tokens; address warp-uniform -> smem broadcast
            float4 av0 = *reinterpret_cast<const float4*>(
                &xs[(d0 + dd) * BM + ty * TM]);
            float4 av1 = *reinterpret_cast<const float4*>(
                &xs[(d0 + dd) * BM + ty * TM + 4]);
            float a_[TM] = { av0.x, av0.y, av0.z, av0.w,
                             av1.x, av1.y, av1.z, av1.w };
            // B fragment: codes q*128 + tx*4 (+0..3); 32 lanes x 16B linear
            float2 bp[TN / 2];
            #pragma unroll
            for (int q = 0; q < 2; q++) {
                float4 bv = *reinterpret_cast<const float4*>(
                    &cb_s[dd * BN + q * 128 + tx * 4]);
                bp[q * 2]     = make_float2(bv.x, bv.y);
                bp[q * 2 + 1] = make_float2(bv.z, bv.w);
            }
            #pragma unroll
            for (int i = 0; i < TM; i++) {
                float2 pa = make_float2(a_[i], a_[i]);
                #pragma unroll
                for (int jp = 0; jp < TN / 2; jp++)
                    acc[i][jp] = ffma2(pa, bp[jp], acc[i][jp]);
            }
        }

        // Tile epilogue: subtract 0.5||c||^2 HERE (exact contract arithmetic),
        // running argmax. Within-thread visit order ascending n, strict '>'
        // keeps lowest index on exact ties.
        if ((c & 7) == 7) {
            const int n0 = (2 * h + (c >> 3)) * BN;
            #pragma unroll
            for (int q = 0; q < 2; q++) {
                const int n = n0 + q * 128 + tx * 4;
                float4 cn = *reinterpret_cast<const float4*>(&g_cnorm_half[n]);
                const float cn_[4] = { cn.x, cn.y, cn.z, cn.w };
                #pragma unroll
                for (int j2 = 0; j2 < 2; j2++) {
                    #pragma unroll
                    for (int i = 0; i < TM; i++) {
                        float s0 = acc[i][q * 2 + j2].x - cn_[j2 * 2];
                        float s1 = acc[i][q * 2 + j2].y - cn_[j2 * 2 + 1];
                        if (s0 > bestv[i]) { bestv[i] = s0; besti[i] = n + j2 * 2; }
                        if (s1 > bestv[i]) { bestv[i] = s1; besti[i] = n + j2 * 2 + 1; }
                    }
                }
            }
        }

        __syncthreads();                  // all threads done reading buf c&1
        if (tid == 0 && c + 2 < NCHUNK) { // refill it with chunk c+2
            MBAR_EXPECT_TX(mbar, CHUNK_BYTES);
            cp_bulk(cs_u + (c & 1) * CHUNK_BYTES,
                    g_cbC + (16 * h + c + 2) * CHUNK_FLOATS, CHUNK_BYTES, mbar);
        }
    }

    // Cross-thread argmax reduce over the 32 tx lanes (tie-break -> lowest
    // idx), then emit per-half partials. (cs is idle: all bulk traffic into it
    // has been consumed and the final __syncthreads above has run.)
    float* rv = cs;                                   // [BM][32]
    int*   ri = reinterpret_cast<int*>(cs + BM * 32); // [BM][32]
    #pragma unroll
    for (int i = 0; i < TM; i++) {
        int m = ty * TM + i;
        rv[m * 32 + tx] = bestv[i];
        ri[m * 32 + tx] = besti[i];
    }
    __syncthreads();
    if (tid < BM) {
        float bv = rv[tid * 32];
        int   bi = ri[tid * 32];
        #pragma unroll
        for (int s = 1; s < 32; s++) {
            float v  = rv[tid * 32 + s];
            int   ix = ri[tid * 32 + s];
            if (v > bv || (v == bv && ix < bi)) { bv = v; bi = ix; }
        }
        g_pv[h * TOK_N + m0 + tid] = bv;
        g_pi[h * TOK_N + m0 + tid] = bi;
    }
}

// ---------------------------------------------------------------------------
// Merge halves + gather. Half-0 indices are always lower, so strict '>' on
// half-1's value preserves the lowest-index tie-break.
// Raw reshape => out linear index = n*D + d; written to both z_hat and z_q.
// ---------------------------------------------------------------------------
__global__ void __launch_bounds__(512)
vq_merge(const float* __restrict__ cb, float* __restrict__ out, int halfElems) {
    __shared__ int fidx[BM];
    const int tid = threadIdx.x;
    const int m0 = blockIdx.x * BM;

    if (tid < BM) {
        int m = m0 + tid;
        float v0 = g_pv[m];
        float v1 = g_pv[TOK_N + m];
        fidx[tid] = (v1 > v0) ? g_pi[TOK_N + m] : g_pi[m];
    }
    __syncthreads();

    const float4* cb4 = reinterpret_cast<const float4*>(cb);
    float4* o1 = reinterpret_cast<float4*>(out);
    float4* o2 = reinterpret_cast<float4*>(out + halfElems);
    #pragma unroll 4
    for (int f = tid; f < BM * (DDIM / 4); f += 512) {
        int m  = f >> 6;              // DDIM/4 = 64 float4 per token
        int d4 = f & 63;
        float4 v = cb4[fidx[m] * (DDIM / 4) + d4];
        long long o = (long long)(m0 + m) * (DDIM / 4) + d4;
        o1[o] = v;
        o2[o] = v;
    }
}

// ---------------------------------------------------------------------------
extern "C" void kernel_launch(void* const* d_in, const int* in_sizes, int n_in,
                              void* d_out, int out_size) {
    const float* x  = reinterpret_cast<const float*>(d_in[0]);
    const float* cb = reinterpret_cast<const float*>(d_in[1]);
    if (n_in >= 2 && in_sizes[0] == KCODES * DDIM && in_sizes[1] != KCODES * DDIM) {
        const float* tmp = x; x = cb; cb = tmp;
    }
    float* out = reinterpret_cast<float*>(d_out);
    int halfElems = out_size / 2;     // (z_hat, z_q) concatenated; identical forward

    cudaFuncSetAttribute(vq_partial, cudaFuncAttributeMaxDynamicSharedMemorySize,
                         SMEM_BYTES);

    vq_prep<<<KCODES, 256>>>(cb);
    vq_partial<<<(TOK_N / BM) * 2, NTHREADS, SMEM_BYTES>>>(x);
    vq_merge<<<TOK_N / BM, 512>>>(cb, out, halfElems);
}